// round 1
// baseline (speedup 1.0000x reference)
#include <cuda_runtime.h>
#include <math.h>

#define B_SZ   2
#define LSEQ   1024
#define DM     1024
#define DI     2048
#define DS     16
#define DC     4
#define MROWS  (B_SZ * LSEQ)   // 2048

// ---------------------------------------------------------------------------
// Scratch (no allocations allowed -> __device__ globals)
// ---------------------------------------------------------------------------
__device__ float g_xz[MROWS * 2 * DI];     // in-proj output (x_in | z)   33.5 MB
__device__ float g_xconv[MROWS * DI];      // conv+silu output            16.8 MB
__device__ float g_delta[MROWS * DI];      // softplus(dt)                16.8 MB
__device__ float g_bc[MROWS * 2 * DS];     // B | C                        0.26 MB
__device__ float g_yz[MROWS * DI];         // scan out * silu(z)          16.8 MB
__device__ float g_mmout[MROWS * DM];      // out-proj result              8.4 MB

// ---------------------------------------------------------------------------
// Tiled fp32 GEMM: C[M,N] = A[M,K] @ B[K,N] + bias[N]; EPI=1 applies softplus.
// Block tile 64x64, K-tile 16, 256 threads, 4x4 per-thread tile.
// Requires M%64==0, N%64==0, K%16==0 (true for all uses here).
// ---------------------------------------------------------------------------
template <int EPI>
__global__ __launch_bounds__(256)
void sgemm64(const float* __restrict__ A, const float* __restrict__ Bm,
             const float* __restrict__ bias, float* __restrict__ C,
             int M, int N, int K)
{
    __shared__ float As[16][68];
    __shared__ float Bs[16][68];

    const int tid = threadIdx.x;
    const int bm = blockIdx.y * 64;
    const int bn = blockIdx.x * 64;
    const int tx = tid & 15;          // N direction (x4)
    const int ty = tid >> 4;          // M direction (x4)

    const int arow = tid >> 2;             // 0..63
    const int ak   = (tid & 3) << 2;       // 0,4,8,12
    const int bk   = tid >> 4;             // 0..15
    const int bn4  = (tid & 15) << 2;      // 0..60

    float acc[4][4];
#pragma unroll
    for (int i = 0; i < 4; i++)
#pragma unroll
        for (int j = 0; j < 4; j++) acc[i][j] = 0.f;

    for (int k0 = 0; k0 < K; k0 += 16) {
        float4 av = *(const float4*)(A  + (size_t)(bm + arow) * K + k0 + ak);
        float4 bv = *(const float4*)(Bm + (size_t)(k0 + bk) * N + bn + bn4);
        __syncthreads();
        As[ak + 0][arow] = av.x;
        As[ak + 1][arow] = av.y;
        As[ak + 2][arow] = av.z;
        As[ak + 3][arow] = av.w;
        *(float4*)&Bs[bk][bn4] = bv;
        __syncthreads();
#pragma unroll
        for (int kk = 0; kk < 16; kk++) {
            float a0 = As[kk][ty * 4 + 0];
            float a1 = As[kk][ty * 4 + 1];
            float a2 = As[kk][ty * 4 + 2];
            float a3 = As[kk][ty * 4 + 3];
            float4 b = *(const float4*)&Bs[kk][tx * 4];
            acc[0][0] += a0 * b.x; acc[0][1] += a0 * b.y; acc[0][2] += a0 * b.z; acc[0][3] += a0 * b.w;
            acc[1][0] += a1 * b.x; acc[1][1] += a1 * b.y; acc[1][2] += a1 * b.z; acc[1][3] += a1 * b.w;
            acc[2][0] += a2 * b.x; acc[2][1] += a2 * b.y; acc[2][2] += a2 * b.z; acc[2][3] += a2 * b.w;
            acc[3][0] += a3 * b.x; acc[3][1] += a3 * b.y; acc[3][2] += a3 * b.z; acc[3][3] += a3 * b.w;
        }
    }

    float4 bsv = *(const float4*)(bias + bn + tx * 4);
#pragma unroll
    for (int i = 0; i < 4; i++) {
        int row = bm + ty * 4 + i;
        float4 v;
        v.x = acc[i][0] + bsv.x;
        v.y = acc[i][1] + bsv.y;
        v.z = acc[i][2] + bsv.z;
        v.w = acc[i][3] + bsv.w;
        if (EPI == 1) {  // softplus
            v.x = (v.x > 15.f) ? v.x : log1pf(__expf(v.x));
            v.y = (v.y > 15.f) ? v.y : log1pf(__expf(v.y));
            v.z = (v.z > 15.f) ? v.z : log1pf(__expf(v.z));
            v.w = (v.w > 15.f) ? v.w : log1pf(__expf(v.w));
        }
        *(float4*)(C + (size_t)row * N + bn + tx * 4) = v;
    }
}

// ---------------------------------------------------------------------------
// Depthwise causal conv (width 4) + SiLU.  x_in = g_xz[..., :DI]
// ---------------------------------------------------------------------------
__global__ void conv_silu(const float* __restrict__ cw, const float* __restrict__ cb)
{
    int idx = blockIdx.x * 256 + threadIdx.x;       // over MROWS*DI
    if (idx >= MROWS * DI) return;
    int d  = idx & (DI - 1);
    int lm = idx >> 11;                             // b*L + l  (DI = 2048)
    int l  = lm & (LSEQ - 1);

    const float* xp = g_xz + (size_t)lm * (2 * DI) + d;
    float acc = cb[d];
#pragma unroll
    for (int j = 0; j < 4; j++) {
        int ll = l - 3 + j;
        if (ll >= 0) acc += xp[(j - 3) * (2 * DI)] * cw[d * 4 + j];
    }
    g_xconv[idx] = acc / (1.f + __expf(-acc));      // silu
}

// ---------------------------------------------------------------------------
// Small projection: g_bc[M,32] = g_xconv[M,2048] @ W_xp[2048,32] + b_xp
// Block: 8 M-rows x 32 cols; W staged through smem in 256-k chunks.
// ---------------------------------------------------------------------------
__global__ __launch_bounds__(256)
void proj_bc(const float* __restrict__ W, const float* __restrict__ bias)
{
    __shared__ float Ws[256 * 32];                  // 32 KB
    int m = blockIdx.x * 8 + (threadIdx.x >> 5);
    int n = threadIdx.x & 31;
    const float* a = g_xconv + (size_t)m * DI;
    float acc = bias[n];
    for (int k0 = 0; k0 < DI; k0 += 256) {
        __syncthreads();
        for (int i = threadIdx.x; i < 256 * 32; i += 256)
            Ws[i] = W[(size_t)k0 * 32 + i];
        __syncthreads();
#pragma unroll 8
        for (int kk = 0; kk < 256; kk++)
            acc += a[k0 + kk] * Ws[kk * 32 + n];
    }
    g_bc[(size_t)m * 32 + n] = acc;
}

// ---------------------------------------------------------------------------
// Selective scan. One 16-lane group per (b,d) channel; lane = state index.
// Fuses: A = -exp(A_log), h-recurrence, C-contraction, +D*x, * silu(z).
// ---------------------------------------------------------------------------
__global__ __launch_bounds__(128)
void scan_kernel(const float* __restrict__ A_log, const float* __restrict__ D_skip)
{
    int grp = threadIdx.x >> 4;                     // 0..7
    int s   = threadIdx.x & 15;                     // state
    int g   = blockIdx.x * 8 + grp;                 // 0 .. B*DI-1
    int b   = g >> 11;                              // / DI
    int d   = g & (DI - 1);

    float Av = -__expf(A_log[d * DS + s]);
    float Dv = D_skip[d];
    float h  = 0.f;

    const float* dp = g_delta + (size_t)b * LSEQ * DI + d;
    const float* xp = g_xconv + (size_t)b * LSEQ * DI + d;
    const float* zp = g_xz + (size_t)b * LSEQ * (2 * DI) + DI + d;
    const float* bcp = g_bc + (size_t)b * LSEQ * (2 * DS);
    float* yp = g_yz + (size_t)b * LSEQ * DI + d;

    for (int t = 0; t < LSEQ; t++) {
        float dv = dp[(size_t)t * DI];
        float xv = xp[(size_t)t * DI];
        float Bv = bcp[t * 32 + s];
        float Cv = bcp[t * 32 + 16 + s];
        float dA = __expf(dv * Av);
        h = fmaf(dA, h, dv * xv * Bv);
        float p = h * Cv;
        p += __shfl_xor_sync(0xffffffffu, p, 8);
        p += __shfl_xor_sync(0xffffffffu, p, 4);
        p += __shfl_xor_sync(0xffffffffu, p, 2);
        p += __shfl_xor_sync(0xffffffffu, p, 1);
        if (s == 0) {
            float y = p + Dv * xv;
            float z = zp[(size_t)t * (2 * DI)];
            yp[(size_t)t * DI] = y * (z / (1.f + __expf(-z)));
        }
    }
}

// ---------------------------------------------------------------------------
// residual add + LayerNorm (unbiased std, eps added to std)
// One block (256 threads) per row of 1024.
// ---------------------------------------------------------------------------
__global__ __launch_bounds__(256)
void add_layernorm(const float* __restrict__ res, const float* __restrict__ alpha,
                   const float* __restrict__ beta, float* __restrict__ out)
{
    __shared__ float red[8];
    int row = blockIdx.x;
    int tid = threadIdx.x;

    float loc[4];
    float s = 0.f;
#pragma unroll
    for (int j = 0; j < 4; j++) {
        int i = tid + j * 256;
        loc[j] = res[(size_t)row * DM + i] + g_mmout[(size_t)row * DM + i];
        s += loc[j];
    }
#pragma unroll
    for (int o = 16; o; o >>= 1) s += __shfl_xor_sync(0xffffffffu, s, o);
    if ((tid & 31) == 0) red[tid >> 5] = s;
    __syncthreads();
    float tot = red[0];
#pragma unroll
    for (int i = 1; i < 8; i++) tot += red[i];
    float mean = tot * (1.f / DM);
    __syncthreads();

    float q = 0.f;
#pragma unroll
    for (int j = 0; j < 4; j++) {
        float df = loc[j] - mean;
        q += df * df;
    }
#pragma unroll
    for (int o = 16; o; o >>= 1) q += __shfl_xor_sync(0xffffffffu, q, o);
    if ((tid & 31) == 0) red[tid >> 5] = q;
    __syncthreads();
    float qt = red[0];
#pragma unroll
    for (int i = 1; i < 8; i++) qt += red[i];

    float stdv = sqrtf(qt * (1.f / (DM - 1)));
    float inv = 1.f / (stdv + 1e-6f);
#pragma unroll
    for (int j = 0; j < 4; j++) {
        int i = tid + j * 256;
        out[(size_t)row * DM + i] = alpha[i] * (loc[j] - mean) * inv + beta[i];
    }
}

// ---------------------------------------------------------------------------
// Launch sequence
// Inputs: 0 x, 1 W_in, 2 b_in, 3 conv_w, 4 conv_b, 5 W_xp, 6 b_xp,
//         7 W_dt, 8 b_dt, 9 A_log, 10 D_skip, 11 W_out, 12 b_out,
//         13 alpha, 14 beta
// ---------------------------------------------------------------------------
extern "C" void kernel_launch(void* const* d_in, const int* in_sizes, int n_in,
                              void* d_out, int out_size)
{
    const float* x      = (const float*)d_in[0];
    const float* W_in   = (const float*)d_in[1];
    const float* b_in   = (const float*)d_in[2];
    const float* conv_w = (const float*)d_in[3];
    const float* conv_b = (const float*)d_in[4];
    const float* W_xp   = (const float*)d_in[5];
    const float* b_xp   = (const float*)d_in[6];
    const float* W_dt   = (const float*)d_in[7];
    const float* b_dt   = (const float*)d_in[8];
    const float* A_log  = (const float*)d_in[9];
    const float* D_skip = (const float*)d_in[10];
    const float* W_out  = (const float*)d_in[11];
    const float* b_out  = (const float*)d_in[12];
    const float* alpha  = (const float*)d_in[13];
    const float* beta   = (const float*)d_in[14];
    float* out = (float*)d_out;

    float *xz, *xconv, *delta, *yz, *mmout;
    cudaGetSymbolAddress((void**)&xz,    g_xz);
    cudaGetSymbolAddress((void**)&xconv, g_xconv);
    cudaGetSymbolAddress((void**)&delta, g_delta);
    cudaGetSymbolAddress((void**)&yz,    g_yz);
    cudaGetSymbolAddress((void**)&mmout, g_mmout);

    // 1) in-proj: xz = x @ W_in + b_in           (2048 x 1024 x 4096)
    sgemm64<0><<<dim3((2 * DI) / 64, MROWS / 64), 256>>>(x, W_in, b_in, xz,
                                                         MROWS, 2 * DI, DM);
    // 2) depthwise causal conv + silu
    conv_silu<<<(MROWS * DI) / 256, 256>>>(conv_w, conv_b);

    // 3) B,C projection                          (2048 x 2048 x 32)
    proj_bc<<<MROWS / 8, 256>>>(W_xp, b_xp);

    // 4) delta = softplus(x_conv @ W_dt + b_dt)  (2048 x 2048 x 2048)
    sgemm64<1><<<dim3(DI / 64, MROWS / 64), 256>>>(xconv, W_dt, b_dt, delta,
                                                   MROWS, DI, DI);
    // 5) selective scan + gate
    scan_kernel<<<(B_SZ * DI) / 8, 128>>>(A_log, D_skip);

    // 6) out-proj                                (2048 x 2048 x 1024)
    sgemm64<0><<<dim3(DM / 64, MROWS / 64), 256>>>(yz, W_out, b_out, mmout,
                                                   MROWS, DM, DI);
    // 7) residual + layernorm
    add_layernorm<<<MROWS, 256>>>(x, alpha, beta, out);
}

// round 3
// speedup vs baseline: 2.0116x; 2.0116x over previous
#include <cuda_runtime.h>
#include <math.h>
#include <stdint.h>

#define B_SZ   2
#define LSEQ   1024
#define DM     1024
#define DI     2048
#define DS     16
#define MROWS  (B_SZ * LSEQ)   // 2048

// ---------------------------------------------------------------------------
// Scratch (__device__ globals; no allocations allowed)
// ---------------------------------------------------------------------------
__device__ float g_xz[MROWS * 2 * DI];
__device__ float g_xconv[MROWS * DI];
__device__ float g_delta[MROWS * DI];
__device__ float g_bc[MROWS * 2 * DS];
__device__ float g_yz[MROWS * DI];
__device__ float g_mmout[MROWS * DM];
__device__ float g_xr[MROWS * DM];          // tf32-rounded x
__device__ float g_wt_in[(2 * DI) * DM];    // W_in^T  [4096,1024] (tf32-rounded)
__device__ float g_wt_dt[DI * DI];          // W_dt^T  [2048,2048]
__device__ float g_wt_out[DM * DI];         // W_out^T [1024,2048]

// ---------------------------------------------------------------------------
// helpers
// ---------------------------------------------------------------------------
static __device__ __forceinline__ float tf32r(float f) {
    uint32_t u;
    asm("cvt.rna.tf32.f32 %0, %1;" : "=r"(u) : "f"(f));
    return __uint_as_float(u);
}
static __device__ __forceinline__ uint32_t smem_u32(const void* p) {
    uint32_t a;
    asm("{ .reg .u64 t; cvta.to.shared.u64 t, %1; cvt.u32.u64 %0, t; }"
        : "=r"(a) : "l"(p));
    return a;
}
static __device__ __forceinline__ void cp_async16(uint32_t sa, const void* ga) {
    asm volatile("cp.async.cg.shared.global [%0], [%1], 16;" :: "r"(sa), "l"(ga));
}
static __device__ __forceinline__ void cp_commit() {
    asm volatile("cp.async.commit_group;" ::: "memory");
}
static __device__ __forceinline__ void cp_wait1() {
    asm volatile("cp.async.wait_group 1;" ::: "memory");
}
static __device__ __forceinline__ void cp_wait0() {
    asm volatile("cp.async.wait_group 0;" ::: "memory");
}
static __device__ __forceinline__ void mma1688(float* d, const uint32_t* a,
                                               const uint32_t* b) {
    asm volatile(
        "mma.sync.aligned.m16n8k8.row.col.f32.tf32.tf32.f32 "
        "{%0,%1,%2,%3}, {%4,%5,%6,%7}, {%8,%9}, {%0,%1,%2,%3};"
        : "+f"(d[0]), "+f"(d[1]), "+f"(d[2]), "+f"(d[3])
        : "r"(a[0]), "r"(a[1]), "r"(a[2]), "r"(a[3]), "r"(b[0]), "r"(b[1]));
}

// ---------------------------------------------------------------------------
// tf32 mma.sync GEMM: C[M,N] = A[M,K] @ Bt[N,K]^T + bias; EPI=1 -> softplus.
// Block 128x128, BK=32, 2-stage cp.async, 256 thr (8 warps, 2x4), warp 64x32.
// A, Bt must be pre-rounded to tf32. M%128==0, N%128==0, K%32==0.
// ---------------------------------------------------------------------------
#define BM 128
#define BN 128
#define BK 32
#define STRD 36                        // floats per smem row (conflict-free)
#define ATILE (BM * STRD)              // 4608 floats
#define BTILE (BN * STRD)
#define GSMEM ((ATILE + BTILE) * 2 * 4)  // 73728 bytes

template <int EPI>
__global__ __launch_bounds__(256, 2)
void gemm_mma(const float* __restrict__ A, const float* __restrict__ Bt,
              const float* __restrict__ bias, float* __restrict__ C,
              int M, int N, int K)
{
    extern __shared__ float sm[];
    float* As = sm;                    // [2][BM][STRD]
    float* Bs = sm + 2 * ATILE;        // [2][BN][STRD]

    const int tid  = threadIdx.x;
    const int lane = tid & 31;
    const int wid  = tid >> 5;
    const int wm   = (wid >> 2) * 64;  // warp m offset
    const int wn   = (wid & 3) * 32;   // warp n offset
    const int bm = blockIdx.y * BM;
    const int bn = blockIdx.x * BN;

    float acc[4][4][4];
#pragma unroll
    for (int mi = 0; mi < 4; mi++)
#pragma unroll
        for (int ni = 0; ni < 4; ni++)
#pragma unroll
            for (int r = 0; r < 4; r++) acc[mi][ni][r] = 0.f;

    auto load_tile = [&](int j) {
        const int stg = j & 1;
        const int k0 = j * BK;
        float* ad = As + stg * ATILE;
        float* bd = Bs + stg * BTILE;
#pragma unroll
        for (int q = 0; q < 4; q++) {
            int ch = tid + q * 256;
            int row = ch >> 3, col = ch & 7;
            cp_async16(smem_u32(ad + row * STRD + col * 4),
                       A + (size_t)(bm + row) * K + k0 + col * 4);
        }
#pragma unroll
        for (int q = 0; q < 4; q++) {
            int ch = tid + q * 256;
            int row = ch >> 3, col = ch & 7;
            cp_async16(smem_u32(bd + row * STRD + col * 4),
                       Bt + (size_t)(bn + row) * K + k0 + col * 4);
        }
    };

    const int KT = K / BK;
    load_tile(0);
    cp_commit();

    for (int i = 0; i < KT; i++) {
        if (i + 1 < KT) {
            load_tile(i + 1);
            cp_commit();
            cp_wait1();
        } else {
            cp_wait0();
        }
        __syncthreads();

        const int stg = i & 1;
        const float* ad = As + stg * ATILE;
        const float* bd = Bs + stg * BTILE;

#pragma unroll
        for (int kk = 0; kk < BK; kk += 8) {
            uint32_t af[4][4];
            uint32_t bf[4][2];
#pragma unroll
            for (int mi = 0; mi < 4; mi++) {
                const float* p = ad + (wm + mi * 16 + (lane >> 2)) * STRD
                                 + kk + (lane & 3);
                af[mi][0] = __float_as_uint(p[0]);
                af[mi][1] = __float_as_uint(p[8 * STRD]);
                af[mi][2] = __float_as_uint(p[4]);
                af[mi][3] = __float_as_uint(p[8 * STRD + 4]);
            }
#pragma unroll
            for (int ni = 0; ni < 4; ni++) {
                const float* p = bd + (wn + ni * 8 + (lane >> 2)) * STRD
                                 + kk + (lane & 3);
                bf[ni][0] = __float_as_uint(p[0]);
                bf[ni][1] = __float_as_uint(p[4]);
            }
#pragma unroll
            for (int mi = 0; mi < 4; mi++)
#pragma unroll
                for (int ni = 0; ni < 4; ni++)
                    mma1688(acc[mi][ni], af[mi], bf[ni]);
        }
        __syncthreads();
    }

    // ---- epilogue ---------------------------------------------------------
#pragma unroll
    for (int mi = 0; mi < 4; mi++) {
#pragma unroll
        for (int ni = 0; ni < 4; ni++) {
            int r0 = bm + wm + mi * 16 + (lane >> 2);
            int c0 = bn + wn + ni * 8 + (lane & 3) * 2;
            float2 bv = *(const float2*)(bias + c0);
            float2 v0, v1;
            v0.x = acc[mi][ni][0] + bv.x;
            v0.y = acc[mi][ni][1] + bv.y;
            v1.x = acc[mi][ni][2] + bv.x;
            v1.y = acc[mi][ni][3] + bv.y;
            if (EPI == 1) {
                v0.x = (v0.x > 15.f) ? v0.x : log1pf(__expf(v0.x));
                v0.y = (v0.y > 15.f) ? v0.y : log1pf(__expf(v0.y));
                v1.x = (v1.x > 15.f) ? v1.x : log1pf(__expf(v1.x));
                v1.y = (v1.y > 15.f) ? v1.y : log1pf(__expf(v1.y));
            }
            *(float2*)(C + (size_t)r0 * N + c0) = v0;
            *(float2*)(C + (size_t)(r0 + 8) * N + c0) = v1;
        }
    }
}

// ---------------------------------------------------------------------------
// tf32 rounding copy (for x)
// ---------------------------------------------------------------------------
__global__ __launch_bounds__(256)
void round_copy(const float* __restrict__ in, float* __restrict__ out, int n)
{
    int i = blockIdx.x * 256 + threadIdx.x;
    if (i < n) out[i] = tf32r(in[i]);
}

// ---------------------------------------------------------------------------
// Weight transpose + tf32 rounding: Wt[n,k] = tf32(W[k,n])
// ---------------------------------------------------------------------------
__global__ __launch_bounds__(256)
void transposeW(const float* __restrict__ W, float* __restrict__ Wt, int K, int N)
{
    __shared__ float t[32][33];
    int n0 = blockIdx.x * 32, k0 = blockIdx.y * 32;
    int tx = threadIdx.x & 31, ty = threadIdx.x >> 5;
#pragma unroll
    for (int i = ty; i < 32; i += 8)
        t[i][tx] = W[(size_t)(k0 + i) * N + n0 + tx];
    __syncthreads();
#pragma unroll
    for (int i = ty; i < 32; i += 8)
        Wt[(size_t)(n0 + i) * K + k0 + tx] = tf32r(t[tx][i]);
}

// ---------------------------------------------------------------------------
// Depthwise causal conv (width 4) + SiLU; output tf32-rounded (GEMM2 operand)
// ---------------------------------------------------------------------------
__global__ void conv_silu(const float* __restrict__ cw, const float* __restrict__ cb)
{
    int idx = blockIdx.x * 256 + threadIdx.x;
    if (idx >= MROWS * DI) return;
    int d  = idx & (DI - 1);
    int lm = idx >> 11;
    int l  = lm & (LSEQ - 1);

    const float* xp = g_xz + (size_t)lm * (2 * DI) + d;
    float acc = cb[d];
#pragma unroll
    for (int j = 0; j < 4; j++) {
        int ll = l - 3 + j;
        if (ll >= 0) acc += xp[(j - 3) * (2 * DI)] * cw[d * 4 + j];
    }
    g_xconv[idx] = tf32r(acc / (1.f + __expf(-acc)));
}

// ---------------------------------------------------------------------------
// B,C projection (K=2048, N=32), fp32
// ---------------------------------------------------------------------------
__global__ __launch_bounds__(256)
void proj_bc(const float* __restrict__ W, const float* __restrict__ bias)
{
    __shared__ float Ws[256 * 32];
    int m = blockIdx.x * 8 + (threadIdx.x >> 5);
    int n = threadIdx.x & 31;
    const float* a = g_xconv + (size_t)m * DI;
    float acc = bias[n];
    for (int k0 = 0; k0 < DI; k0 += 256) {
        __syncthreads();
        for (int i = threadIdx.x; i < 256 * 32; i += 256)
            Ws[i] = W[(size_t)k0 * 32 + i];
        __syncthreads();
#pragma unroll 8
        for (int kk = 0; kk < 256; kk++)
            acc += a[k0 + kk] * Ws[kk * 32 + n];
    }
    g_bc[(size_t)m * 32 + n] = acc;
}

// ---------------------------------------------------------------------------
// Selective scan + gate (software-pipelined loads); output tf32-rounded
// ---------------------------------------------------------------------------
__global__ __launch_bounds__(128)
void scan_kernel(const float* __restrict__ A_log, const float* __restrict__ D_skip)
{
    int grp = threadIdx.x >> 4;
    int s   = threadIdx.x & 15;
    int g   = blockIdx.x * 8 + grp;
    int b   = g >> 11;
    int d   = g & (DI - 1);

    float Av = -__expf(A_log[d * DS + s]);
    float Dv = D_skip[d];
    float h  = 0.f;

    const float* dp  = g_delta + (size_t)b * LSEQ * DI + d;
    const float* xp  = g_xconv + (size_t)b * LSEQ * DI + d;
    const float* zp  = g_xz + (size_t)b * LSEQ * (2 * DI) + DI + d;
    const float* bcp = g_bc + (size_t)b * LSEQ * (2 * DS);
    float* yp = g_yz + (size_t)b * LSEQ * DI + d;

    float dv = dp[0];
    float xv = xp[0];
    float Bv = bcp[s];
    float Cv = bcp[16 + s];

    for (int t = 0; t < LSEQ; t++) {
        float dvn = 0.f, xvn = 0.f, Bvn = 0.f, Cvn = 0.f;
        if (t + 1 < LSEQ) {
            dvn = dp[(size_t)(t + 1) * DI];
            xvn = xp[(size_t)(t + 1) * DI];
            Bvn = bcp[(t + 1) * 32 + s];
            Cvn = bcp[(t + 1) * 32 + 16 + s];
        }
        float dA = __expf(dv * Av);
        h = fmaf(dA, h, dv * xv * Bv);
        float p = h * Cv;
        p += __shfl_xor_sync(0xffffffffu, p, 8);
        p += __shfl_xor_sync(0xffffffffu, p, 4);
        p += __shfl_xor_sync(0xffffffffu, p, 2);
        p += __shfl_xor_sync(0xffffffffu, p, 1);
        if (s == 0) {
            float y = p + Dv * xv;
            float z = zp[(size_t)t * (2 * DI)];
            yp[(size_t)t * DI] = tf32r(y * (z / (1.f + __expf(-z))));
        }
        dv = dvn; xv = xvn; Bv = Bvn; Cv = Cvn;
    }
}

// ---------------------------------------------------------------------------
// residual add + LayerNorm (unbiased std, eps added to std)
// ---------------------------------------------------------------------------
__global__ __launch_bounds__(256)
void add_layernorm(const float* __restrict__ res, const float* __restrict__ alpha,
                   const float* __restrict__ beta, float* __restrict__ out)
{
    __shared__ float red[8];
    int row = blockIdx.x;
    int tid = threadIdx.x;

    float loc[4];
    float sgm = 0.f;
#pragma unroll
    for (int j = 0; j < 4; j++) {
        int i = tid + j * 256;
        loc[j] = res[(size_t)row * DM + i] + g_mmout[(size_t)row * DM + i];
        sgm += loc[j];
    }
#pragma unroll
    for (int o = 16; o; o >>= 1) sgm += __shfl_xor_sync(0xffffffffu, sgm, o);
    if ((tid & 31) == 0) red[tid >> 5] = sgm;
    __syncthreads();
    float tot = red[0];
#pragma unroll
    for (int i = 1; i < 8; i++) tot += red[i];
    float mean = tot * (1.f / DM);
    __syncthreads();

    float q = 0.f;
#pragma unroll
    for (int j = 0; j < 4; j++) {
        float df = loc[j] - mean;
        q += df * df;
    }
#pragma unroll
    for (int o = 16; o; o >>= 1) q += __shfl_xor_sync(0xffffffffu, q, o);
    if ((tid & 31) == 0) red[tid >> 5] = q;
    __syncthreads();
    float qt = red[0];
#pragma unroll
    for (int i = 1; i < 8; i++) qt += red[i];

    float stdv = sqrtf(qt * (1.f / (DM - 1)));
    float inv = 1.f / (stdv + 1e-6f);
#pragma unroll
    for (int j = 0; j < 4; j++) {
        int i = tid + j * 256;
        out[(size_t)row * DM + i] = alpha[i] * (loc[j] - mean) * inv + beta[i];
    }
}

// ---------------------------------------------------------------------------
// Launch sequence
// ---------------------------------------------------------------------------
extern "C" void kernel_launch(void* const* d_in, const int* in_sizes, int n_in,
                              void* d_out, int out_size)
{
    const float* x      = (const float*)d_in[0];
    const float* W_in   = (const float*)d_in[1];
    const float* b_in   = (const float*)d_in[2];
    const float* conv_w = (const float*)d_in[3];
    const float* conv_b = (const float*)d_in[4];
    const float* W_xp   = (const float*)d_in[5];
    const float* b_xp   = (const float*)d_in[6];
    const float* W_dt   = (const float*)d_in[7];
    const float* b_dt   = (const float*)d_in[8];
    const float* A_log  = (const float*)d_in[9];
    const float* D_skip = (const float*)d_in[10];
    const float* W_out  = (const float*)d_in[11];
    const float* b_out  = (const float*)d_in[12];
    const float* alpha  = (const float*)d_in[13];
    const float* beta   = (const float*)d_in[14];
    float* out = (float*)d_out;

    float *xz, *xconv, *delta, *yz, *mmout, *xr, *wt_in, *wt_dt, *wt_out;
    cudaGetSymbolAddress((void**)&xz,     g_xz);
    cudaGetSymbolAddress((void**)&xconv,  g_xconv);
    cudaGetSymbolAddress((void**)&delta,  g_delta);
    cudaGetSymbolAddress((void**)&yz,     g_yz);
    cudaGetSymbolAddress((void**)&mmout,  g_mmout);
    cudaGetSymbolAddress((void**)&xr,     g_xr);
    cudaGetSymbolAddress((void**)&wt_in,  g_wt_in);
    cudaGetSymbolAddress((void**)&wt_dt,  g_wt_dt);
    cudaGetSymbolAddress((void**)&wt_out, g_wt_out);

    cudaFuncSetAttribute(gemm_mma<0>, cudaFuncAttributeMaxDynamicSharedMemorySize, GSMEM);
    cudaFuncSetAttribute(gemm_mma<1>, cudaFuncAttributeMaxDynamicSharedMemorySize, GSMEM);

    // operand prep (tf32 rounding)
    round_copy<<<(MROWS * DM + 255) / 256, 256>>>(x, xr, MROWS * DM);
    transposeW<<<dim3((2 * DI) / 32, DM / 32), 256>>>(W_in,  wt_in,  DM, 2 * DI);
    transposeW<<<dim3(DI / 32, DI / 32),        256>>>(W_dt,  wt_dt,  DI, DI);
    transposeW<<<dim3(DM / 32, DI / 32),        256>>>(W_out, wt_out, DI, DM);

    // 1) in-proj: xz = x @ W_in + b_in     (M=2048, N=4096, K=1024)
    gemm_mma<0><<<dim3((2 * DI) / BN, MROWS / BM), 256, GSMEM>>>(
        xr, wt_in, b_in, xz, MROWS, 2 * DI, DM);

    // 2) depthwise causal conv + silu
    conv_silu<<<(MROWS * DI) / 256, 256>>>(conv_w, conv_b);

    // 3) B,C projection
    proj_bc<<<MROWS / 8, 256>>>(W_xp, b_xp);

    // 4) delta = softplus(x_conv @ W_dt + b_dt)  (2048 x 2048 x 2048)
    gemm_mma<1><<<dim3(DI / BN, MROWS / BM), 256, GSMEM>>>(
        xconv, wt_dt, b_dt, delta, MROWS, DI, DI);

    // 5) selective scan + gate
    scan_kernel<<<(B_SZ * DI) / 8, 128>>>(A_log, D_skip);

    // 6) out-proj                                (2048 x 1024 x 2048)
    gemm_mma<0><<<dim3(DM / BN, MROWS / BM), 256, GSMEM>>>(
        yz, wt_out, b_out, mmout, MROWS, DM, DI);

    // 7) residual + layernorm
    add_layernorm<<<MROWS, 256>>>(x, alpha, beta, out);
}